// round 1
// baseline (speedup 1.0000x reference)
#include <cuda_runtime.h>

#define B_  8
#define C_  512
#define H_  8
#define DH  64
#define N_  1024

// Scratch (allocation-free rule: __device__ globals)
__device__ float g_q[(size_t)B_ * C_ * N_];
__device__ float g_k[(size_t)B_ * C_ * N_];
__device__ float g_v[(size_t)B_ * C_ * N_];
__device__ float g_s[(size_t)B_ * H_ * N_ * N_];   // 256 MB scores/attn

// ---------------------------------------------------------------------------
// Kernel A: QKV projection.  out[o,n] = sum_c W[o,c] * X[c,n] + bias[o]
// grid: (N/128, C/128, B*3), block 256, 128x128 tile, 8x8 per thread
// ---------------------------------------------------------------------------
__global__ __launch_bounds__(256, 2) void qkv_gemm(
    const float* __restrict__ x,
    const float* __restrict__ wq, const float* __restrict__ bq,
    const float* __restrict__ wk, const float* __restrict__ bk,
    const float* __restrict__ wv, const float* __restrict__ bv)
{
    const int bz  = blockIdx.z;
    const int b   = bz / 3;
    const int sel = bz - b * 3;

    const float* W;
    const float* bias;
    float* out;
    if (sel == 0)      { W = wq; bias = bq; out = g_q; }
    else if (sel == 1) { W = wk; bias = bk; out = g_k; }
    else               { W = wv; bias = bv; out = g_v; }
    out += (size_t)b * C_ * N_;
    const float* X = x + (size_t)b * C_ * N_;

    const int o0 = blockIdx.y * 128;
    const int n0 = blockIdx.x * 128;
    const int t  = threadIdx.x;
    const int tx = t & 15, ty = t >> 4;

    __shared__ float As[8][128];
    __shared__ float Bs[8][128];

    float acc[8][8];
#pragma unroll
    for (int i = 0; i < 8; i++)
#pragma unroll
        for (int j = 0; j < 8; j++) acc[i][j] = 0.f;

    const int arow = t >> 1, acg = t & 1;   // A tile: 128 rows x 2 float4
    const int brow = t >> 5, bcg = t & 31;  // B tile: 8 rows x 32 float4

    for (int kt = 0; kt < C_ / 8; kt++) {
        float4 w4 = *(const float4*)&W[(size_t)(o0 + arow) * C_ + kt * 8 + acg * 4];
        float4 x4 = *(const float4*)&X[(size_t)(kt * 8 + brow) * N_ + n0 + bcg * 4];
        As[acg * 4 + 0][arow] = w4.x;
        As[acg * 4 + 1][arow] = w4.y;
        As[acg * 4 + 2][arow] = w4.z;
        As[acg * 4 + 3][arow] = w4.w;
        *(float4*)&Bs[brow][bcg * 4] = x4;
        __syncthreads();
#pragma unroll
        for (int k = 0; k < 8; k++) {
            float4 a0 = *(const float4*)&As[k][ty * 4];
            float4 a1 = *(const float4*)&As[k][64 + ty * 4];
            float4 b0 = *(const float4*)&Bs[k][tx * 4];
            float4 b1 = *(const float4*)&Bs[k][64 + tx * 4];
            float ar[8] = {a0.x, a0.y, a0.z, a0.w, a1.x, a1.y, a1.z, a1.w};
            float br[8] = {b0.x, b0.y, b0.z, b0.w, b1.x, b1.y, b1.z, b1.w};
#pragma unroll
            for (int i = 0; i < 8; i++)
#pragma unroll
                for (int j = 0; j < 8; j++)
                    acc[i][j] = fmaf(ar[i], br[j], acc[i][j]);
        }
        __syncthreads();
    }

#pragma unroll
    for (int ib = 0; ib < 2; ib++)
#pragma unroll
        for (int i = 0; i < 4; i++) {
            int o = o0 + ib * 64 + ty * 4 + i;
            float bb = bias[o];
#pragma unroll
            for (int jb = 0; jb < 2; jb++) {
                float4 r;
                r.x = acc[ib * 4 + i][jb * 4 + 0] + bb;
                r.y = acc[ib * 4 + i][jb * 4 + 1] + bb;
                r.z = acc[ib * 4 + i][jb * 4 + 2] + bb;
                r.w = acc[ib * 4 + i][jb * 4 + 3] + bb;
                *(float4*)&out[(size_t)o * N_ + n0 + jb * 64 + tx * 4] = r;
            }
        }
}

// ---------------------------------------------------------------------------
// Kernel B: scores.  S[n,m] = sum_d q[d,n]k[d,m] + sum_d pos[d,n]q[d,m]
// Augmented K-dim 128: A'[kk,n] = kk<64 ? q[kk,n] : pos[kk-64,n]
//                      B'[kk,m] = kk<64 ? k[kk,m] : q[kk-64,m]
// grid: (N/128, N/128, B*H), block 256
// ---------------------------------------------------------------------------
__global__ __launch_bounds__(256, 2) void score_gemm(
    const float* __restrict__ rh, const float* __restrict__ rw)
{
    const int bh = blockIdx.z;
    const int b = bh >> 3, h = bh & 7;
    const float* q  = g_q + ((size_t)b * C_ + h * DH) * N_;
    const float* kp = g_k + ((size_t)b * C_ + h * DH) * N_;
    float* S = g_s + (size_t)bh * N_ * N_;

    const int n0 = blockIdx.y * 128;   // rows of S (query index n)
    const int m0 = blockIdx.x * 128;   // cols of S (softmax axis m)
    const int t  = threadIdx.x;
    const int tx = t & 15, ty = t >> 4;
    const int krow = t >> 5, cg = t & 31;

    __shared__ float As[8][128];
    __shared__ float Bs[8][128];

    float acc[8][8];
#pragma unroll
    for (int i = 0; i < 8; i++)
#pragma unroll
        for (int j = 0; j < 8; j++) acc[i][j] = 0.f;

    for (int kt = 0; kt < 16; kt++) {
        int kk = kt * 8 + krow;
        float4 av, bv;
        if (kk < DH) {
            av = *(const float4*)&q[(size_t)kk * N_ + n0 + cg * 4];
            bv = *(const float4*)&kp[(size_t)kk * N_ + m0 + cg * 4];
        } else {
            int d = kk - DH;
            const float* rhp = rh + (h * DH + d) * 32;
            const float* rwp = rw + (h * DH + d) * 32;
            int nb = n0 + cg * 4;
            float rr = rwp[nb >> 5];
            int jj = nb & 31;          // nb % 4 == 0, so jj+3 <= 31
            av.x = rhp[jj + 0] + rr;
            av.y = rhp[jj + 1] + rr;
            av.z = rhp[jj + 2] + rr;
            av.w = rhp[jj + 3] + rr;
            bv = *(const float4*)&q[(size_t)d * N_ + m0 + cg * 4];
        }
        *(float4*)&As[krow][cg * 4] = av;
        *(float4*)&Bs[krow][cg * 4] = bv;
        __syncthreads();
#pragma unroll
        for (int k = 0; k < 8; k++) {
            float4 a0 = *(const float4*)&As[k][ty * 4];
            float4 a1 = *(const float4*)&As[k][64 + ty * 4];
            float4 b0 = *(const float4*)&Bs[k][tx * 4];
            float4 b1 = *(const float4*)&Bs[k][64 + tx * 4];
            float ar[8] = {a0.x, a0.y, a0.z, a0.w, a1.x, a1.y, a1.z, a1.w};
            float br[8] = {b0.x, b0.y, b0.z, b0.w, b1.x, b1.y, b1.z, b1.w};
#pragma unroll
            for (int i = 0; i < 8; i++)
#pragma unroll
                for (int j = 0; j < 8; j++)
                    acc[i][j] = fmaf(ar[i], br[j], acc[i][j]);
        }
        __syncthreads();
    }

#pragma unroll
    for (int ib = 0; ib < 2; ib++)
#pragma unroll
        for (int i = 0; i < 4; i++) {
            int n = n0 + ib * 64 + ty * 4 + i;
#pragma unroll
            for (int jb = 0; jb < 2; jb++) {
                float4 r;
                r.x = acc[ib * 4 + i][jb * 4 + 0];
                r.y = acc[ib * 4 + i][jb * 4 + 1];
                r.z = acc[ib * 4 + i][jb * 4 + 2];
                r.w = acc[ib * 4 + i][jb * 4 + 3];
                *(float4*)&S[(size_t)n * N_ + m0 + jb * 64 + tx * 4] = r;
            }
        }
}

// ---------------------------------------------------------------------------
// Kernel C: row softmax in-place on g_s.  grid = B*H*N rows, block 256
// ---------------------------------------------------------------------------
__global__ __launch_bounds__(256) void softmax_k()
{
    float* S = g_s + (size_t)blockIdx.x * N_;
    const int t = threadIdx.x;

    float v0 = S[t], v1 = S[t + 256], v2 = S[t + 512], v3 = S[t + 768];
    float mx = fmaxf(fmaxf(v0, v1), fmaxf(v2, v3));

    __shared__ float red[16];
#pragma unroll
    for (int o = 16; o; o >>= 1) mx = fmaxf(mx, __shfl_xor_sync(0xffffffffu, mx, o));
    if ((t & 31) == 0) red[t >> 5] = mx;
    __syncthreads();
    mx = fmaxf(fmaxf(fmaxf(red[0], red[1]), fmaxf(red[2], red[3])),
               fmaxf(fmaxf(red[4], red[5]), fmaxf(red[6], red[7])));

    v0 = __expf(v0 - mx);
    v1 = __expf(v1 - mx);
    v2 = __expf(v2 - mx);
    v3 = __expf(v3 - mx);
    float s = v0 + v1 + v2 + v3;
#pragma unroll
    for (int o = 16; o; o >>= 1) s += __shfl_xor_sync(0xffffffffu, s, o);
    if ((t & 31) == 0) red[8 + (t >> 5)] = s;
    __syncthreads();
    s = (red[8] + red[9]) + (red[10] + red[11]) + (red[12] + red[13]) + (red[14] + red[15]);

    float inv = 1.f / s;
    S[t]       = v0 * inv;
    S[t + 256] = v1 * inv;
    S[t + 512] = v2 * inv;
    S[t + 768] = v3 * inv;
}

// ---------------------------------------------------------------------------
// Kernel D: output.  y[d,m] = sum_n v[d,n] * attn[m,n]
// grid: (N/128, B*H), block 256, tile 64(d) x 128(m), K-tile 16 over n
// ---------------------------------------------------------------------------
__global__ __launch_bounds__(256, 2) void out_gemm(float* __restrict__ out)
{
    const int bh = blockIdx.y;
    const int b = bh >> 3, h = bh & 7;
    const float* V = g_v + ((size_t)b * C_ + h * DH) * N_;
    const float* A = g_s + (size_t)bh * N_ * N_;
    float* O = out + ((size_t)b * C_ + h * DH) * N_;

    const int m0 = blockIdx.x * 128;
    const int t  = threadIdx.x;
    const int tx = t & 15, ty = t >> 4;

    __shared__ float Vs[16][68];    // padded, 272B row = 16B aligned
    __shared__ float As[16][132];   // padded, 528B row = 16B aligned

    float acc[4][8];
#pragma unroll
    for (int i = 0; i < 4; i++)
#pragma unroll
        for (int j = 0; j < 8; j++) acc[i][j] = 0.f;

    const int vd = t >> 2, vk = t & 3;  // 64 d-rows x 4 k-groups

    for (int kt = 0; kt < 64; kt++) {
        int nb = kt * 16;
        float4 vv = *(const float4*)&V[(size_t)vd * N_ + nb + vk * 4];
        float4 a0 = *(const float4*)&A[(size_t)(m0 + (t >> 2)) * N_ + nb + (t & 3) * 4];
        float4 a1 = *(const float4*)&A[(size_t)(m0 + 64 + (t >> 2)) * N_ + nb + (t & 3) * 4];

        Vs[vk * 4 + 0][vd] = vv.x;
        Vs[vk * 4 + 1][vd] = vv.y;
        Vs[vk * 4 + 2][vd] = vv.z;
        Vs[vk * 4 + 3][vd] = vv.w;
        int kg = (t & 3) * 4, mm = t >> 2;
        As[kg + 0][mm] = a0.x;  As[kg + 1][mm] = a0.y;
        As[kg + 2][mm] = a0.z;  As[kg + 3][mm] = a0.w;
        As[kg + 0][64 + mm] = a1.x;  As[kg + 1][64 + mm] = a1.y;
        As[kg + 2][64 + mm] = a1.z;  As[kg + 3][64 + mm] = a1.w;
        __syncthreads();
#pragma unroll
        for (int k = 0; k < 16; k++) {
            float4 a  = *(const float4*)&Vs[k][ty * 4];
            float4 b0 = *(const float4*)&As[k][tx * 4];
            float4 b1 = *(const float4*)&As[k][64 + tx * 4];
            float ar[4] = {a.x, a.y, a.z, a.w};
            float br[8] = {b0.x, b0.y, b0.z, b0.w, b1.x, b1.y, b1.z, b1.w};
#pragma unroll
            for (int i = 0; i < 4; i++)
#pragma unroll
                for (int j = 0; j < 8; j++)
                    acc[i][j] = fmaf(ar[i], br[j], acc[i][j]);
        }
        __syncthreads();
    }

#pragma unroll
    for (int i = 0; i < 4; i++) {
        int d = ty * 4 + i;
#pragma unroll
        for (int jb = 0; jb < 2; jb++) {
            float4 r;
            r.x = acc[i][jb * 4 + 0];
            r.y = acc[i][jb * 4 + 1];
            r.z = acc[i][jb * 4 + 2];
            r.w = acc[i][jb * 4 + 3];
            *(float4*)&O[(size_t)d * N_ + m0 + jb * 64 + tx * 4] = r;
        }
    }
}

// ---------------------------------------------------------------------------
extern "C" void kernel_launch(void* const* d_in, const int* in_sizes, int n_in,
                              void* d_out, int out_size)
{
    const float* x  = (const float*)d_in[0];
    const float* wq = (const float*)d_in[1];
    const float* bq = (const float*)d_in[2];
    const float* wk = (const float*)d_in[3];
    const float* bk = (const float*)d_in[4];
    const float* wv = (const float*)d_in[5];
    const float* bv = (const float*)d_in[6];
    const float* rh = (const float*)d_in[7];
    const float* rw = (const float*)d_in[8];

    qkv_gemm<<<dim3(N_ / 128, C_ / 128, B_ * 3), 256>>>(x, wq, bq, wk, bk, wv, bv);
    score_gemm<<<dim3(N_ / 128, N_ / 128, B_ * H_), 256>>>(rh, rw);
    softmax_k<<<B_ * H_ * N_, 256>>>();
    out_gemm<<<dim3(N_ / 128, B_ * H_), 256>>>((float*)d_out);
}

// round 3
// speedup vs baseline: 2.5638x; 2.5638x over previous
#include <cuda_runtime.h>
#include <cuda_fp16.h>
#include <cstdint>

#define B_  8
#define C_  512
#define H_  8
#define DH  64
#define N_  1024
#define BH_ 64

// ---------------- scratch (__device__ globals; no allocs) ----------------
__device__ __half g_Wh[3 * C_ * C_], g_Wl[3 * C_ * C_];          // [sel][o][c]
__device__ __half g_XTh[B_ * N_ * C_], g_XTl[B_ * N_ * C_];      // [b][n][c]
__device__ __half g_ph[H_ * N_ * DH], g_pl[H_ * N_ * DH];        // [h][n][d]
__device__ __half g_qh[BH_ * N_ * DH], g_ql[BH_ * N_ * DH];      // [bh][n][d]
__device__ __half g_kh[BH_ * N_ * DH], g_kl[BH_ * N_ * DH];      // [bh][n][d]
__device__ __half g_v[(size_t)B_ * C_ * N_];                     // [b][c][n]

// ---------------- helpers ----------------
__device__ __forceinline__ uint32_t s2u(const void* p) {
    uint32_t a;
    asm("{ .reg .u64 t; cvta.to.shared.u64 t, %1; cvt.u32.u64 %0, t; }" : "=r"(a) : "l"(p));
    return a;
}
__device__ __forceinline__ void cpasync16(uint32_t dst, const void* src) {
    asm volatile("cp.async.ca.shared.global [%0], [%1], 16;" :: "r"(dst), "l"(src));
}
__device__ __forceinline__ void cp_commit() {
    asm volatile("cp.async.commit_group;" ::: "memory");
}
__device__ __forceinline__ void cp_wait0() {
    asm volatile("cp.async.wait_group 0;" ::: "memory");
}
__device__ __forceinline__ void cp_wait1() {
    asm volatile("cp.async.wait_group 1;" ::: "memory");
}
__device__ __forceinline__ void ldsm4(uint32_t* r, uint32_t addr) {
    asm volatile("ldmatrix.sync.aligned.m8n8.x4.shared.b16 {%0,%1,%2,%3}, [%4];"
                 : "=r"(r[0]), "=r"(r[1]), "=r"(r[2]), "=r"(r[3]) : "r"(addr));
}
__device__ __forceinline__ void mma_f16(float* c, const uint32_t* a, const uint32_t* b) {
    asm volatile(
        "mma.sync.aligned.m16n8k16.row.col.f32.f16.f16.f32 "
        "{%0,%1,%2,%3},{%4,%5,%6,%7},{%8,%9},{%0,%1,%2,%3};"
        : "+f"(c[0]), "+f"(c[1]), "+f"(c[2]), "+f"(c[3])
        : "r"(a[0]), "r"(a[1]), "r"(a[2]), "r"(a[3]), "r"(b[0]), "r"(b[1]));
}
// 128B-row tiles ([rows][64] half), XOR swizzle on 16B granules
__device__ __forceinline__ uint32_t swz(uint32_t base, int row, int g) {
    return base + row * 128 + ((g ^ (row & 7)) << 4);
}
// 256B-row tiles ([rows][128] half)
__device__ __forceinline__ uint32_t swzv(uint32_t base, int row, int g) {
    return base + row * 256 + ((g ^ (row & 7)) << 4);
}
__device__ __forceinline__ void split_h(float a, __half& h, __half& l) {
    h = __float2half_rn(a);
    l = __float2half_rn(a - __half2float(h));
}
__device__ __forceinline__ uint32_t pack2(float a, float b) {
    __half2 h = __floats2half2_rn(a, b);
    return *(uint32_t*)&h;
}

// ---------------- prep kernels ----------------
__global__ __launch_bounds__(256) void prep_w(const float* __restrict__ wq,
                                              const float* __restrict__ wk,
                                              const float* __restrict__ wv) {
    int idx = blockIdx.x * 256 + threadIdx.x;
    int sel = idx >> 18, rc = idx & 262143;
    const float* W = sel == 0 ? wq : (sel == 1 ? wk : wv);
    __half h, l;
    split_h(W[rc], h, l);
    g_Wh[idx] = h; g_Wl[idx] = l;
}

__global__ void prep_xt(const float* __restrict__ x) {
    __shared__ float sm[32][33];
    int b = blockIdx.z, c0 = blockIdx.y * 32, n0 = blockIdx.x * 32;
    int tx = threadIdx.x, ty = threadIdx.y;
    sm[ty][tx] = x[((size_t)b * C_ + c0 + ty) * N_ + n0 + tx];
    __syncthreads();
    __half h, l;
    split_h(sm[tx][ty], h, l);
    size_t off = ((size_t)b * N_ + n0 + ty) * C_ + c0 + tx;
    g_XTh[off] = h; g_XTl[off] = l;
}

__global__ __launch_bounds__(256) void prep_pos(const float* __restrict__ rh,
                                                const float* __restrict__ rw) {
    int idx = blockIdx.x * 256 + threadIdx.x;   // [h][n][d]
    int d = idx & 63, n = (idx >> 6) & 1023, h = idx >> 16;
    float a = rh[(h * DH + d) * 32 + (n & 31)] + rw[(h * DH + d) * 32 + (n >> 5)];
    __half hh, ll;
    split_h(a, hh, ll);
    g_ph[idx] = hh; g_pl[idx] = ll;
}

// ---------------- stage 1: QKV projection (mma.sync, hi/lo 3-term) -------
// out[o,n] = sum_c W[o,c] x[c,n] + bias[o]; computed as (XT @ W^T)
// grid (8 ntiles, 4 otiles, 24=b*3), 256 thr = 8 warps (4m x 2n), tile 128x128
#define SMEM_QKV 65536
__global__ __launch_bounds__(256) void qkv_mma(const float* __restrict__ bq,
                                               const float* __restrict__ bk,
                                               const float* __restrict__ bv) {
    extern __shared__ char smem[];
    uint32_t sb = s2u(smem);
    int t = threadIdx.x, lane = t & 31, wid = t >> 5;
    int wm = wid >> 1, wn = wid & 1;
    int n0 = blockIdx.x * 128, o0 = blockIdx.y * 128;
    int z = blockIdx.z, b = z / 3, sel = z - b * 3;

    const __half* XH = g_XTh + (size_t)b * N_ * C_;
    const __half* XL = g_XTl + (size_t)b * N_ * C_;
    const __half* WH = g_Wh + (size_t)sel * C_ * C_;
    const __half* WL = g_Wl + (size_t)sel * C_ * C_;

    float acc[2][8][4];
#pragma unroll
    for (int i = 0; i < 2; i++)
#pragma unroll
        for (int j = 0; j < 8; j++)
#pragma unroll
            for (int k = 0; k < 4; k++) acc[i][j][k] = 0.f;

    auto issue = [&](int c, int buf) {
        int term = c >> 3, cc = c & 7;
        const __half* As = (term == 2 ? XL : XH) + (size_t)n0 * C_ + cc * 64;
        const __half* Bs = (term == 1 ? WL : WH) + (size_t)o0 * C_ + cc * 64;
        uint32_t ab = sb + buf * 32768, bb = ab + 16384;
#pragma unroll
        for (int i = 0; i < 4; i++) {
            int idx = t + i * 256;              // 0..1023
            int row = idx >> 3, g = idx & 7;
            cpasync16(swz(ab, row, g), As + (size_t)row * C_ + g * 8);
            cpasync16(swz(bb, row, g), Bs + (size_t)row * C_ + g * 8);
        }
        cp_commit();
    };

    issue(0, 0);
    for (int c = 0; c < 24; c++) {
        if (c < 23) { issue(c + 1, (c + 1) & 1); cp_wait1(); }
        else cp_wait0();
        __syncthreads();
        uint32_t ab = sb + (c & 1) * 32768, bb = ab + 16384;
#pragma unroll
        for (int ks = 0; ks < 4; ks++) {
            uint32_t a[2][4];
#pragma unroll
            for (int mi = 0; mi < 2; mi++)
                ldsm4(a[mi], swz(ab, wm * 32 + mi * 16 + (lane & 15), 2 * ks + (lane >> 4)));
#pragma unroll
            for (int nb = 0; nb < 4; nb++) {
                uint32_t bf[4];
                ldsm4(bf, swz(bb, wn * 64 + nb * 16 + (lane & 15), 2 * ks + (lane >> 4)));
                uint32_t blo[2] = {bf[0], bf[2]}, bhi[2] = {bf[1], bf[3]};
#pragma unroll
                for (int mi = 0; mi < 2; mi++) {
                    mma_f16(acc[mi][nb * 2], a[mi], blo);
                    mma_f16(acc[mi][nb * 2 + 1], a[mi], bhi);
                }
            }
        }
        __syncthreads();
    }

    const float* bias = sel == 0 ? bq : (sel == 1 ? bk : bv);
#pragma unroll
    for (int mi = 0; mi < 2; mi++)
#pragma unroll
        for (int nf = 0; nf < 8; nf++) {
            int col = wn * 64 + nf * 8 + (lane & 3) * 2;
            int og = o0 + col;
            float b0 = bias[og], b1 = bias[og + 1];
            int r0 = n0 + wm * 32 + mi * 16 + (lane >> 2);
            float v0 = acc[mi][nf][0] + b0, v1 = acc[mi][nf][1] + b1;
            float v2 = acc[mi][nf][2] + b0, v3 = acc[mi][nf][3] + b1;
            if (sel == 2) {
                __half* vp = g_v + ((size_t)b * C_ + og) * N_;
                vp[r0] = __float2half_rn(v0);
                vp[r0 + 8] = __float2half_rn(v2);
                vp[N_ + r0] = __float2half_rn(v1);
                vp[N_ + r0 + 8] = __float2half_rn(v3);
            } else {
                int hh = og >> 6, d = og & 63;
                __half* TH = (sel ? g_kh : g_qh) + (size_t)(b * H_ + hh) * N_ * DH;
                __half* TL = (sel ? g_kl : g_ql) + (size_t)(b * H_ + hh) * N_ * DH;
                __half h0, l0, h1, l1;
                split_h(v0, h0, l0); split_h(v1, h1, l1);
                *(__half2*)&TH[(size_t)r0 * DH + d] = __halves2half2(h0, h1);
                *(__half2*)&TL[(size_t)r0 * DH + d] = __halves2half2(l0, l1);
                split_h(v2, h0, l0); split_h(v3, h1, l1);
                *(__half2*)&TH[(size_t)(r0 + 8) * DH + d] = __halves2half2(h0, h1);
                *(__half2*)&TL[(size_t)(r0 + 8) * DH + d] = __halves2half2(l0, l1);
            }
        }
}

// ---------------- stage 2-4 fused flash attention -------------------------
// per CTA: one bh, one 128-query tile; 8 warps, warp w owns query rows 16w..16w+15
#define A_QH 0
#define A_QL 16384
#define A_PH 32768
#define A_PL 49152
#define B_KH 65536
#define B_KL 81920
#define B_QH 98304
#define B_QL 114688
#define B_V  131072
#define SMEM_FU 147456
__global__ __launch_bounds__(256) void attn_fused(float* __restrict__ out) {
    extern __shared__ char smem[];
    uint32_t sb = s2u(smem);
    int t = threadIdx.x, lane = t & 31, w = t >> 5;
    int q0 = blockIdx.x * 128;
    int bh = blockIdx.y, b = bh >> 3, h = bh & 7;

    const __half* QH = g_qh + (size_t)bh * N_ * DH;
    const __half* QL = g_ql + (size_t)bh * N_ * DH;
    const __half* KH = g_kh + (size_t)bh * N_ * DH;
    const __half* KL = g_kl + (size_t)bh * N_ * DH;
    const __half* PH = g_ph + (size_t)h * N_ * DH;
    const __half* PL = g_pl + (size_t)h * N_ * DH;
    const __half* V  = g_v + (size_t)(b * C_ + h * DH) * N_;   // [64][1024]

    // load A region (query-side): qh,ql,ph,pl tiles rows q0..q0+127
    {
        const __half* srcs[4] = {QH, QL, PH, PL};
#pragma unroll
        for (int i = 0; i < 4; i++) {
            const __half* src = srcs[i] + (size_t)q0 * DH;
            uint32_t base = sb + i * 16384;
#pragma unroll
            for (int p = 0; p < 4; p++) {
                int idx = t + p * 256;
                int row = idx >> 3, g = idx & 7;
                cpasync16(swz(base, row, g), src + (size_t)row * DH + g * 8);
            }
        }
        cp_commit();
    }

    float m0 = -1e30f, m1 = -1e30f, l0 = 0.f, l1 = 0.f;
    float y[8][4];
#pragma unroll
    for (int i = 0; i < 8; i++)
#pragma unroll
        for (int j = 0; j < 4; j++) y[i][j] = 0.f;

    for (int j = 0; j < 8; j++) {
        int n0 = j * 128;
        {
            const __half* srcs[4] = {KH, KL, QH, QL};
#pragma unroll
            for (int i = 0; i < 4; i++) {
                const __half* src = srcs[i] + (size_t)n0 * DH;
                uint32_t base = sb + B_KH + i * 16384;
#pragma unroll
                for (int p = 0; p < 4; p++) {
                    int idx = t + p * 256;
                    int row = idx >> 3, g = idx & 7;
                    cpasync16(swz(base, row, g), src + (size_t)row * DH + g * 8);
                }
            }
#pragma unroll
            for (int p = 0; p < 4; p++) {
                int idx = t + p * 256;
                int row = idx >> 4, g = idx & 15;   // [64][128] tile
                cpasync16(swzv(sb + B_V, row, g), V + (size_t)row * N_ + n0 + g * 8);
            }
            cp_commit();
            cp_wait0();
            __syncthreads();
        }

        // ---- scores: S[m, key] over augmented K = 6 x 64 ----
        float s[16][4];
#pragma unroll
        for (int f = 0; f < 16; f++)
#pragma unroll
            for (int k = 0; k < 4; k++) s[f][k] = 0.f;

        const int Aoff[6] = {A_QH, A_QL, A_QH, A_PH, A_PL, A_PH};
        const int Boff[6] = {B_KH, B_KH, B_KL, B_QH, B_QH, B_QL};
#pragma unroll
        for (int c6 = 0; c6 < 6; c6++) {
            uint32_t abase = sb + Aoff[c6], bbase = sb + Boff[c6];
#pragma unroll
            for (int ks = 0; ks < 4; ks++) {
                uint32_t a[4];
                ldsm4(a, swz(abase, w * 16 + (lane & 15), 2 * ks + (lane >> 4)));
#pragma unroll
                for (int nb = 0; nb < 8; nb++) {
                    uint32_t bf[4];
                    ldsm4(bf, swz(bbase, nb * 16 + (lane & 15), 2 * ks + (lane >> 4)));
                    uint32_t blo[2] = {bf[0], bf[2]}, bhi[2] = {bf[1], bf[3]};
                    mma_f16(s[nb * 2], a, blo);
                    mma_f16(s[nb * 2 + 1], a, bhi);
                }
            }
        }

        // ---- online softmax update ----
        float tmax0 = -1e30f, tmax1 = -1e30f;
#pragma unroll
        for (int f = 0; f < 16; f++) {
            tmax0 = fmaxf(tmax0, fmaxf(s[f][0], s[f][1]));
            tmax1 = fmaxf(tmax1, fmaxf(s[f][2], s[f][3]));
        }
        tmax0 = fmaxf(tmax0, __shfl_xor_sync(0xffffffffu, tmax0, 1));
        tmax0 = fmaxf(tmax0, __shfl_xor_sync(0xffffffffu, tmax0, 2));
        tmax1 = fmaxf(tmax1, __shfl_xor_sync(0xffffffffu, tmax1, 1));
        tmax1 = fmaxf(tmax1, __shfl_xor_sync(0xffffffffu, tmax1, 2));
        float mn0 = fmaxf(m0, tmax0), mn1 = fmaxf(m1, tmax1);
        float sc0 = __expf(m0 - mn0), sc1 = __expf(m1 - mn1);
        m0 = mn0; m1 = mn1;

        float ts0 = 0.f, ts1 = 0.f;
        uint32_t pf[16][2];
#pragma unroll
        for (int f = 0; f < 16; f++) {
            float p0 = __expf(s[f][0] - mn0), p1 = __expf(s[f][1] - mn0);
            float p2 = __expf(s[f][2] - mn1), p3 = __expf(s[f][3] - mn1);
            ts0 += p0 + p1; ts1 += p2 + p3;
            pf[f][0] = pack2(p0, p1);
            pf[f][1] = pack2(p2, p3);
        }
        ts0 += __shfl_xor_sync(0xffffffffu, ts0, 1);
        ts0 += __shfl_xor_sync(0xffffffffu, ts0, 2);
        ts1 += __shfl_xor_sync(0xffffffffu, ts1, 1);
        ts1 += __shfl_xor_sync(0xffffffffu, ts1, 2);
        l0 = l0 * sc0 + ts0;
        l1 = l1 * sc1 + ts1;
#pragma unroll
        for (int nf = 0; nf < 8; nf++) {
            y[nf][0] *= sc0; y[nf][1] *= sc0;
            y[nf][2] *= sc1; y[nf][3] *= sc1;
        }

        // ---- y += P @ V^T  (B from v smem [d][key]) ----
#pragma unroll
        for (int ks = 0; ks < 8; ks++) {
            uint32_t a[4] = {pf[2 * ks][0], pf[2 * ks][1], pf[2 * ks + 1][0], pf[2 * ks + 1][1]};
#pragma unroll
            for (int nb = 0; nb < 4; nb++) {
                uint32_t bf[4];
                ldsm4(bf, swzv(sb + B_V, nb * 16 + (lane & 15), 2 * ks + (lane >> 4)));
                uint32_t blo[2] = {bf[0], bf[2]}, bhi[2] = {bf[1], bf[3]};
                mma_f16(y[nb * 2], a, blo);
                mma_f16(y[nb * 2 + 1], a, bhi);
            }
        }
        __syncthreads();
    }

    // ---- epilogue: y /= l, transpose-stage, coalesced store ----
    float i0 = 1.f / l0, i1 = 1.f / l1;
    float* yst = (float*)smem;   // reuse A region: [64][132]
    int q = w * 16 + (lane >> 2);
#pragma unroll
    for (int nf = 0; nf < 8; nf++) {
        int d = nf * 8 + (lane & 3) * 2;
        yst[d * 132 + q] = y[nf][0] * i0;
        yst[(d + 1) * 132 + q] = y[nf][1] * i0;
        yst[d * 132 + q + 8] = y[nf][2] * i1;
        yst[(d + 1) * 132 + q + 8] = y[nf][3] * i1;
    }
    __syncthreads();
    float* O = out + (size_t)(b * C_ + h * DH) * N_ + q0;
    for (int i = t; i < 2048; i += 256) {
        int d = i >> 5, qg = i & 31;
        float4 vv = *(float4*)&yst[d * 132 + qg * 4];
        *(float4*)&O[(size_t)d * N_ + qg * 4] = vv;
    }
}

// ---------------- launch ----------------
extern "C" void kernel_launch(void* const* d_in, const int* in_sizes, int n_in,
                              void* d_out, int out_size) {
    const float* x  = (const float*)d_in[0];
    const float* wq = (const float*)d_in[1];
    const float* bq = (const float*)d_in[2];
    const float* wk = (const float*)d_in[3];
    const float* bk = (const float*)d_in[4];
    const float* wv = (const float*)d_in[5];
    const float* bv = (const float*)d_in[6];
    const float* rh = (const float*)d_in[7];
    const float* rw = (const float*)d_in[8];

    cudaFuncSetAttribute(qkv_mma, cudaFuncAttributeMaxDynamicSharedMemorySize, SMEM_QKV);
    cudaFuncSetAttribute(attn_fused, cudaFuncAttributeMaxDynamicSharedMemorySize, SMEM_FU);

    prep_w<<<(3 * C_ * C_) / 256, 256>>>(wq, wk, wv);
    prep_xt<<<dim3(N_ / 32, C_ / 32, B_), dim3(32, 32)>>>(x);
    prep_pos<<<(H_ * N_ * DH) / 256, 256>>>(rh, rw);

    qkv_mma<<<dim3(8, 4, 24), 256, SMEM_QKV>>>(bq, bk, bv);
    attn_fused<<<dim3(8, BH_), 256, SMEM_FU>>>((float*)d_out);
}

// round 4
// speedup vs baseline: 2.7520x; 1.0734x over previous
#include <cuda_runtime.h>
#include <cuda_fp16.h>
#include <cstdint>

#define B_  8
#define C_  512
#define H_  8
#define DH  64
#define N_  1024
#define BH_ 64

// ---------------- scratch (__device__ globals; no allocs) ----------------
__device__ __half g_Wh[3 * C_ * C_], g_Wl[3 * C_ * C_];          // [sel][o][c]
__device__ __half g_XTh[B_ * N_ * C_], g_XTl[B_ * N_ * C_];      // [b][n][c]
__device__ __half g_ph[H_ * N_ * DH], g_pl[H_ * N_ * DH];        // [h][n][d]
__device__ __half g_qh[BH_ * N_ * DH], g_ql[BH_ * N_ * DH];      // [bh][n][d]
__device__ __half g_kh[BH_ * N_ * DH], g_kl[BH_ * N_ * DH];      // [bh][n][d]
__device__ __half g_v[(size_t)B_ * C_ * N_];                     // [b][c][n]

// ---------------- helpers ----------------
__device__ __forceinline__ uint32_t s2u(const void* p) {
    uint32_t a;
    asm("{ .reg .u64 t; cvta.to.shared.u64 t, %1; cvt.u32.u64 %0, t; }" : "=r"(a) : "l"(p));
    return a;
}
__device__ __forceinline__ void cpasync16(uint32_t dst, const void* src) {
    asm volatile("cp.async.ca.shared.global [%0], [%1], 16;" :: "r"(dst), "l"(src));
}
__device__ __forceinline__ void cp_commit() {
    asm volatile("cp.async.commit_group;" ::: "memory");
}
__device__ __forceinline__ void cp_wait0() {
    asm volatile("cp.async.wait_group 0;" ::: "memory");
}
__device__ __forceinline__ void ldsm4(uint32_t* r, uint32_t addr) {
    asm volatile("ldmatrix.sync.aligned.m8n8.x4.shared.b16 {%0,%1,%2,%3}, [%4];"
                 : "=r"(r[0]), "=r"(r[1]), "=r"(r[2]), "=r"(r[3]) : "r"(addr));
}
__device__ __forceinline__ void mma_f16(float* c, const uint32_t* a, const uint32_t* b) {
    asm volatile(
        "mma.sync.aligned.m16n8k16.row.col.f32.f16.f16.f32 "
        "{%0,%1,%2,%3},{%4,%5,%6,%7},{%8,%9},{%0,%1,%2,%3};"
        : "+f"(c[0]), "+f"(c[1]), "+f"(c[2]), "+f"(c[3])
        : "r"(a[0]), "r"(a[1]), "r"(a[2]), "r"(a[3]), "r"(b[0]), "r"(b[1]));
}
// 128B-row tiles ([rows][64] half), XOR swizzle on 16B granules
__device__ __forceinline__ uint32_t swz(uint32_t base, int row, int g) {
    return base + row * 128 + ((g ^ (row & 7)) << 4);
}
// 256B-row tiles ([rows][128] half)
__device__ __forceinline__ uint32_t swzv(uint32_t base, int row, int g) {
    return base + row * 256 + ((g ^ (row & 7)) << 4);
}
__device__ __forceinline__ void split_h(float a, __half& h, __half& l) {
    h = __float2half_rn(a);
    l = __float2half_rn(a - __half2float(h));
}
__device__ __forceinline__ uint32_t pack2(float a, float b) {
    __half2 h = __floats2half2_rn(a, b);
    return *(uint32_t*)&h;
}

// ---------------- prep kernels ----------------
__global__ __launch_bounds__(256) void prep_w(const float* __restrict__ wq,
                                              const float* __restrict__ wk,
                                              const float* __restrict__ wv) {
    int idx = blockIdx.x * 256 + threadIdx.x;
    int sel = idx >> 18, rc = idx & 262143;
    const float* W = sel == 0 ? wq : (sel == 1 ? wk : wv);
    __half h, l;
    split_h(W[rc], h, l);
    g_Wh[idx] = h; g_Wl[idx] = l;
}

__global__ void prep_xt(const float* __restrict__ x) {
    __shared__ float sm[32][33];
    int b = blockIdx.z, c0 = blockIdx.y * 32, n0 = blockIdx.x * 32;
    int tx = threadIdx.x, ty = threadIdx.y;
    sm[ty][tx] = x[((size_t)b * C_ + c0 + ty) * N_ + n0 + tx];
    __syncthreads();
    __half h, l;
    split_h(sm[tx][ty], h, l);
    size_t off = ((size_t)b * N_ + n0 + ty) * C_ + c0 + tx;
    g_XTh[off] = h; g_XTl[off] = l;
}

__global__ __launch_bounds__(256) void prep_pos(const float* __restrict__ rh,
                                                const float* __restrict__ rw) {
    int idx = blockIdx.x * 256 + threadIdx.x;   // [h][n][d]
    int d = idx & 63, n = (idx >> 6) & 1023, h = idx >> 16;
    float a = rh[(h * DH + d) * 32 + (n & 31)] + rw[(h * DH + d) * 32 + (n >> 5)];
    __half hh, ll;
    split_h(a, hh, ll);
    g_ph[idx] = hh; g_pl[idx] = ll;
}

// ---------------- stage 1: QKV projection (mma.sync, hi/lo 3-term) -------
// out[o,n] = sum_c W[o,c] x[c,n] + bias[o]; computed as (XT @ W^T)
// per K-chunk (64): load XH,XL,WH,WL once, run 3 terms from same stage.
// stage layout: XH +0, XL +16K, WH +32K, WL +48K ; 2 stages of 64KB.
#define SMEM_QKV 131072
__global__ __launch_bounds__(256) void qkv_mma(const float* __restrict__ bq,
                                               const float* __restrict__ bk,
                                               const float* __restrict__ bv) {
    extern __shared__ char smem[];
    uint32_t sb = s2u(smem);
    int t = threadIdx.x, lane = t & 31, wid = t >> 5;
    int wm = wid >> 1, wn = wid & 1;
    int n0 = blockIdx.x * 128, o0 = blockIdx.y * 128;
    int z = blockIdx.z, b = z / 3, sel = z - b * 3;

    const __half* XH = g_XTh + (size_t)b * N_ * C_ + (size_t)n0 * C_;
    const __half* XL = g_XTl + (size_t)b * N_ * C_ + (size_t)n0 * C_;
    const __half* WH = g_Wh + (size_t)sel * C_ * C_ + (size_t)o0 * C_;
    const __half* WL = g_Wl + (size_t)sel * C_ * C_ + (size_t)o0 * C_;

    float acc[2][8][4];
#pragma unroll
    for (int i = 0; i < 2; i++)
#pragma unroll
        for (int j = 0; j < 8; j++)
#pragma unroll
            for (int k = 0; k < 4; k++) acc[i][j][k] = 0.f;

    auto issue = [&](int cc, int buf) {
        uint32_t st = sb + buf * 65536;
        const __half* srcs[4] = {XH, XL, WH, WL};
#pragma unroll
        for (int i = 0; i < 4; i++) {
            const __half* src = srcs[i] + cc * 64;
#pragma unroll
            for (int p = 0; p < 4; p++) {
                int idx = t + p * 256;
                int row = idx >> 3, g = idx & 7;
                cpasync16(swz(st + i * 16384, row, g), src + (size_t)row * C_ + g * 8);
            }
        }
        cp_commit();
    };

    issue(0, 0);
    for (int cc = 0; cc < 8; cc++) {
        cp_wait0();
        __syncthreads();
        if (cc < 7) issue(cc + 1, (cc + 1) & 1);
        uint32_t st = sb + (cc & 1) * 65536;
#pragma unroll
        for (int ks = 0; ks < 4; ks++) {
            uint32_t aH[2][4], aL[2][4];
#pragma unroll
            for (int mi = 0; mi < 2; mi++) {
                ldsm4(aH[mi], swz(st, wm * 32 + mi * 16 + (lane & 15), 2 * ks + (lane >> 4)));
                ldsm4(aL[mi], swz(st + 16384, wm * 32 + mi * 16 + (lane & 15), 2 * ks + (lane >> 4)));
            }
#pragma unroll
            for (int nb = 0; nb < 4; nb++) {
                uint32_t bH[4], bL[4];
                ldsm4(bH, swz(st + 32768, wn * 64 + nb * 16 + (lane & 15), 2 * ks + (lane >> 4)));
                ldsm4(bL, swz(st + 49152, wn * 64 + nb * 16 + (lane & 15), 2 * ks + (lane >> 4)));
                uint32_t bHlo[2] = {bH[0], bH[2]}, bHhi[2] = {bH[1], bH[3]};
                uint32_t bLlo[2] = {bL[0], bL[2]}, bLhi[2] = {bL[1], bL[3]};
#pragma unroll
                for (int mi = 0; mi < 2; mi++) {
                    mma_f16(acc[mi][nb * 2], aH[mi], bHlo);
                    mma_f16(acc[mi][nb * 2 + 1], aH[mi], bHhi);
                    mma_f16(acc[mi][nb * 2], aH[mi], bLlo);
                    mma_f16(acc[mi][nb * 2 + 1], aH[mi], bLhi);
                    mma_f16(acc[mi][nb * 2], aL[mi], bHlo);
                    mma_f16(acc[mi][nb * 2 + 1], aL[mi], bHhi);
                }
            }
        }
    }

    const float* bias = sel == 0 ? bq : (sel == 1 ? bk : bv);
#pragma unroll
    for (int mi = 0; mi < 2; mi++)
#pragma unroll
        for (int nf = 0; nf < 8; nf++) {
            int col = wn * 64 + nf * 8 + (lane & 3) * 2;
            int og = o0 + col;
            float b0 = bias[og], b1 = bias[og + 1];
            int r0 = n0 + wm * 32 + mi * 16 + (lane >> 2);
            float v0 = acc[mi][nf][0] + b0, v1 = acc[mi][nf][1] + b1;
            float v2 = acc[mi][nf][2] + b0, v3 = acc[mi][nf][3] + b1;
            if (sel == 2) {
                __half* vp = g_v + ((size_t)b * C_ + og) * N_;
                vp[r0] = __float2half_rn(v0);
                vp[r0 + 8] = __float2half_rn(v2);
                vp[N_ + r0] = __float2half_rn(v1);
                vp[N_ + r0 + 8] = __float2half_rn(v3);
            } else {
                int hh = og >> 6, d = og & 63;
                __half* TH = (sel ? g_kh : g_qh) + (size_t)(b * H_ + hh) * N_ * DH;
                __half* TL = (sel ? g_kl : g_ql) + (size_t)(b * H_ + hh) * N_ * DH;
                __half h0, l0, h1, l1;
                split_h(v0, h0, l0); split_h(v1, h1, l1);
                *(__half2*)&TH[(size_t)r0 * DH + d] = __halves2half2(h0, h1);
                *(__half2*)&TL[(size_t)r0 * DH + d] = __halves2half2(l0, l1);
                split_h(v2, h0, l0); split_h(v3, h1, l1);
                *(__half2*)&TH[(size_t)(r0 + 8) * DH + d] = __halves2half2(h0, h1);
                *(__half2*)&TL[(size_t)(r0 + 8) * DH + d] = __halves2half2(l0, l1);
            }
        }
}

// ---------------- stage 2-4 fused flash attention -------------------------
// per CTA: one bh, one 128-query tile; 8 warps, warp w owns query rows 16w..16w+15
// A region (query side) 64KB; B region double-buffered 2 x 80KB:
//   buffer: KH +0, KL +16K, QH +32K, QL +48K, V +64K
#define A_QH 0
#define A_QL 16384
#define A_PH 32768
#define A_PL 49152
#define B_BASE 65536
#define B_STRIDE 81920
#define SMEM_FU 229376
__global__ __launch_bounds__(256) void attn_fused(float* __restrict__ out) {
    extern __shared__ char smem[];
    uint32_t sb = s2u(smem);
    int t = threadIdx.x, lane = t & 31, w = t >> 5;
    int q0 = blockIdx.x * 128;
    int bh = blockIdx.y, b = bh >> 3, h = bh & 7;

    const __half* QH = g_qh + (size_t)bh * N_ * DH;
    const __half* QL = g_ql + (size_t)bh * N_ * DH;
    const __half* KH = g_kh + (size_t)bh * N_ * DH;
    const __half* KL = g_kl + (size_t)bh * N_ * DH;
    const __half* PH = g_ph + (size_t)h * N_ * DH;
    const __half* PL = g_pl + (size_t)h * N_ * DH;
    const __half* V  = g_v + (size_t)(b * C_ + h * DH) * N_;   // [64][1024]

    // A region (query-side): qh,ql,ph,pl rows q0..q0+127
    {
        const __half* srcs[4] = {QH, QL, PH, PL};
#pragma unroll
        for (int i = 0; i < 4; i++) {
            const __half* src = srcs[i] + (size_t)q0 * DH;
            uint32_t base = sb + i * 16384;
#pragma unroll
            for (int p = 0; p < 4; p++) {
                int idx = t + p * 256;
                int row = idx >> 3, g = idx & 7;
                cpasync16(swz(base, row, g), src + (size_t)row * DH + g * 8);
            }
        }
        cp_commit();
    }

    auto prefetch = [&](int j, int p) {
        int n0 = j * 128;
        uint32_t bb = sb + B_BASE + p * B_STRIDE;
        const __half* srcs[4] = {KH, KL, QH, QL};
#pragma unroll
        for (int i = 0; i < 4; i++) {
            const __half* src = srcs[i] + (size_t)n0 * DH;
#pragma unroll
            for (int pp = 0; pp < 4; pp++) {
                int idx = t + pp * 256;
                int row = idx >> 3, g = idx & 7;
                cpasync16(swz(bb + i * 16384, row, g), src + (size_t)row * DH + g * 8);
            }
        }
#pragma unroll
        for (int pp = 0; pp < 4; pp++) {
            int idx = t + pp * 256;
            int row = idx >> 4, g = idx & 15;   // [64][128] tile
            cpasync16(swzv(bb + 65536, row, g), V + (size_t)row * N_ + n0 + g * 8);
        }
        cp_commit();
    };

    prefetch(0, 0);

    float m0 = -1e30f, m1 = -1e30f, l0 = 0.f, l1 = 0.f;
    float y[8][4];
#pragma unroll
    for (int i = 0; i < 8; i++)
#pragma unroll
        for (int j = 0; j < 4; j++) y[i][j] = 0.f;

    for (int j = 0; j < 8; j++) {
        cp_wait0();
        __syncthreads();
        if (j < 7) prefetch(j + 1, (j + 1) & 1);
        uint32_t bb = sb + B_BASE + (j & 1) * B_STRIDE;

        // ---- scores: S[q, key] over augmented hi/lo products ----
        float s[16][4];
#pragma unroll
        for (int f = 0; f < 16; f++)
#pragma unroll
            for (int k = 0; k < 4; k++) s[f][k] = 0.f;

#pragma unroll
        for (int ks = 0; ks < 4; ks++) {
            int arow = w * 16 + (lane & 15), acol = 2 * ks + (lane >> 4);
            uint32_t aQH[4], aQL[4], aPH[4], aPL[4];
            ldsm4(aQH, swz(sb + A_QH, arow, acol));
            ldsm4(aQL, swz(sb + A_QL, arow, acol));
            ldsm4(aPH, swz(sb + A_PH, arow, acol));
            ldsm4(aPL, swz(sb + A_PL, arow, acol));
#pragma unroll
            for (int nb = 0; nb < 8; nb++) {
                int brow = nb * 16 + (lane & 15), bcol = 2 * ks + (lane >> 4);
                uint32_t bKH[4], bKL[4], bQH[4], bQL[4];
                ldsm4(bKH, swz(bb, brow, bcol));
                ldsm4(bKL, swz(bb + 16384, brow, bcol));
                ldsm4(bQH, swz(bb + 32768, brow, bcol));
                ldsm4(bQL, swz(bb + 49152, brow, bcol));
                uint32_t kh_lo[2] = {bKH[0], bKH[2]}, kh_hi[2] = {bKH[1], bKH[3]};
                uint32_t kl_lo[2] = {bKL[0], bKL[2]}, kl_hi[2] = {bKL[1], bKL[3]};
                uint32_t qh_lo[2] = {bQH[0], bQH[2]}, qh_hi[2] = {bQH[1], bQH[3]};
                uint32_t ql_lo[2] = {bQL[0], bQL[2]}, ql_hi[2] = {bQL[1], bQL[3]};
                float* s0 = s[nb * 2];
                float* s1 = s[nb * 2 + 1];
                mma_f16(s0, aQH, kh_lo);  mma_f16(s1, aQH, kh_hi);
                mma_f16(s0, aQL, kh_lo);  mma_f16(s1, aQL, kh_hi);
                mma_f16(s0, aQH, kl_lo);  mma_f16(s1, aQH, kl_hi);
                mma_f16(s0, aPH, qh_lo);  mma_f16(s1, aPH, qh_hi);
                mma_f16(s0, aPL, qh_lo);  mma_f16(s1, aPL, qh_hi);
                mma_f16(s0, aPH, ql_lo);  mma_f16(s1, aPH, ql_hi);
            }
        }

        // ---- online softmax update ----
        float tmax0 = -1e30f, tmax1 = -1e30f;
#pragma unroll
        for (int f = 0; f < 16; f++) {
            tmax0 = fmaxf(tmax0, fmaxf(s[f][0], s[f][1]));
            tmax1 = fmaxf(tmax1, fmaxf(s[f][2], s[f][3]));
        }
        tmax0 = fmaxf(tmax0, __shfl_xor_sync(0xffffffffu, tmax0, 1));
        tmax0 = fmaxf(tmax0, __shfl_xor_sync(0xffffffffu, tmax0, 2));
        tmax1 = fmaxf(tmax1, __shfl_xor_sync(0xffffffffu, tmax1, 1));
        tmax1 = fmaxf(tmax1, __shfl_xor_sync(0xffffffffu, tmax1, 2));
        float mn0 = fmaxf(m0, tmax0), mn1 = fmaxf(m1, tmax1);
        float sc0 = __expf(m0 - mn0), sc1 = __expf(m1 - mn1);
        m0 = mn0; m1 = mn1;

        float ts0 = 0.f, ts1 = 0.f;
        uint32_t pf[16][2];
#pragma unroll
        for (int f = 0; f < 16; f++) {
            float p0 = __expf(s[f][0] - mn0), p1 = __expf(s[f][1] - mn0);
            float p2 = __expf(s[f][2] - mn1), p3 = __expf(s[f][3] - mn1);
            ts0 += p0 + p1; ts1 += p2 + p3;
            pf[f][0] = pack2(p0, p1);
            pf[f][1] = pack2(p2, p3);
        }
        ts0 += __shfl_xor_sync(0xffffffffu, ts0, 1);
        ts0 += __shfl_xor_sync(0xffffffffu, ts0, 2);
        ts1 += __shfl_xor_sync(0xffffffffu, ts1, 1);
        ts1 += __shfl_xor_sync(0xffffffffu, ts1, 2);
        l0 = l0 * sc0 + ts0;
        l1 = l1 * sc1 + ts1;
#pragma unroll
        for (int nf = 0; nf < 8; nf++) {
            y[nf][0] *= sc0; y[nf][1] *= sc0;
            y[nf][2] *= sc1; y[nf][3] *= sc1;
        }

        // ---- y += P @ V^T  (B from v smem [d][key]) ----
#pragma unroll
        for (int ks = 0; ks < 8; ks++) {
            uint32_t a[4] = {pf[2 * ks][0], pf[2 * ks][1], pf[2 * ks + 1][0], pf[2 * ks + 1][1]};
#pragma unroll
            for (int nb = 0; nb < 4; nb++) {
                uint32_t bf[4];
                ldsm4(bf, swzv(bb + 65536, nb * 16 + (lane & 15), 2 * ks + (lane >> 4)));
                uint32_t blo[2] = {bf[0], bf[2]}, bhi[2] = {bf[1], bf[3]};
                mma_f16(y[nb * 2], a, blo);
                mma_f16(y[nb * 2 + 1], a, bhi);
            }
        }
    }

    // ---- epilogue: y /= l, transpose-stage in A region, coalesced store ----
    __syncthreads();
    float i0 = 1.f / l0, i1 = 1.f / l1;
    float* yst = (float*)smem;   // reuse A region: [64][132]
    int q = w * 16 + (lane >> 2);
#pragma unroll
    for (int nf = 0; nf < 8; nf++) {
        int d = nf * 8 + (lane & 3) * 2;
        yst[d * 132 + q] = y[nf][0] * i0;
        yst[(d + 1) * 132 + q] = y[nf][1] * i0;
        yst[d * 132 + q + 8] = y[nf][2] * i1;
        yst[(d + 1) * 132 + q + 8] = y[nf][3] * i1;
    }
    __syncthreads();
    float* O = out + (size_t)(b * C_ + h * DH) * N_ + q0;
    for (int i = t; i < 2048; i += 256) {
        int d = i >> 5, qg = i & 31;
        float4 vv = *(float4*)&yst[d * 132 + qg * 4];
        *(float4*)&O[(size_t)d * N_ + qg * 4] = vv;
    }
}

// ---------------- launch ----------------
extern "C" void kernel_launch(void* const* d_in, const int* in_sizes, int n_in,
                              void* d_out, int out_size) {
    const float* x  = (const float*)d_in[0];
    const float* wq = (const float*)d_in[1];
    const float* bq = (const float*)d_in[2];
    const float* wk = (const float*)d_in[3];
    const float* bk = (const float*)d_in[4];
    const float* wv = (const float*)d_in[5];
    const float* bv = (const float*)d_in[6];
    const float* rh = (const float*)d_in[7];
    const float* rw = (const float*)d_in[8];

    cudaFuncSetAttribute(qkv_mma, cudaFuncAttributeMaxDynamicSharedMemorySize, SMEM_QKV);
    cudaFuncSetAttribute(attn_fused, cudaFuncAttributeMaxDynamicSharedMemorySize, SMEM_FU);

    prep_w<<<(3 * C_ * C_) / 256, 256>>>(wq, wk, wv);
    prep_xt<<<dim3(N_ / 32, C_ / 32, B_), dim3(32, 32)>>>(x);
    prep_pos<<<(H_ * N_ * DH) / 256, 256>>>(rh, rw);

    qkv_mma<<<dim3(8, 4, 24), 256, SMEM_QKV>>>(bq, bk, bv);
    attn_fused<<<dim3(8, BH_), 256, SMEM_FU>>>((float*)d_out);
}